// round 12
// baseline (speedup 1.0000x reference)
#include <cuda_runtime.h>
#include <cuda_bf16.h>

#define SEQ   4096
#define DIM   512
#define DIM1  513
#define PI_F  3.14159265358979f
#define NBLK  1184              // 148 SMs * 8 resident CTAs -> single wave
#define N4    8404992           // 16*4096*513 / 4 output float4s

// Persistent-grid output-vectorized concat, ILP=4.
// Exactly one wave of CTAs (148x8); each thread grid-strides over its float4
// groups so the memory pipeline never drains at a wave boundary.
// Mapping per group (base=i4*4, r=base/513, c=base-513r):
//   output elem j in [0,4):  pe-channel iff j == 512-c
//   input addr             :  r*512 + c + j - (c+j >= 513)
__global__ __launch_bounds__(256) void pe_concat_kernel(
    const float* __restrict__ in,
    const int*   __restrict__ lengths,
    float*       __restrict__ out)
{
    const int stride = NBLK * 1024;              // float4s per grid iteration
    float4* const out4 = reinterpret_cast<float4*>(out);

    for (int i4_0 = blockIdx.x * 1024 + threadIdx.x; i4_0 < N4; i4_0 += stride)
    {
        float4 o[4];
#pragma unroll
        for (int g = 0; g < 4; g++) {
            const int i4 = i4_0 + g * 256;
            if (i4 >= N4) break;                 // only last iteration
            const int base = i4 * 4;
            const int r    = base / DIM1;        // const-div -> mulhi
            const int c    = base - r * DIM1;
            const int kpe  = DIM - c;            // j-index of pe elem (may be >=4)
            const float* p = in + r * DIM + c;

            float v[4];
#pragma unroll
            for (int j = 0; j < 4; j++) {
                const int adj = (j > kpe) ? 1 : 0;   // skip over pe column
                v[j] = (j == kpe) ? 0.0f : __ldg(p + j - adj);
            }

            if (kpe < 4) {                       // ~0.78% of groups
                const int b = r >> 12;           // row / 4096
                const int s = r & (SEQ - 1);     // row % 4096
                const float fl   = (float)__ldg(lengths + b);
                const float safe = fmaxf(fl, 1.0f);
                v[kpe] = ((float)s < fl) ? __cosf(((float)s / safe) * PI_F) : 0.0f;
            }

            o[g].x = v[0]; o[g].y = v[1]; o[g].z = v[2]; o[g].w = v[3];
        }

#pragma unroll
        for (int g = 0; g < 4; g++) {
            const int i4 = i4_0 + g * 256;
            if (i4 < N4) out4[i4] = o[g];
        }
    }
}

extern "C" void kernel_launch(void* const* d_in, const int* in_sizes, int n_in,
                              void* d_out, int out_size)
{
    const float* in      = (const float*)d_in[0];   // [16, 4096, 512] f32
    const int*   lengths = (const int*)  d_in[1];   // [16] i32
    float*       out     = (float*)d_out;           // [16, 4096, 513] f32

    (void)in_sizes; (void)n_in; (void)out_size;
    pe_concat_kernel<<<NBLK, 256>>>(in, lengths, out);
}

// round 13
// speedup vs baseline: 1.0007x; 1.0007x over previous
#include <cuda_runtime.h>
#include <cuda_bf16.h>

#define SEQ   4096
#define DIM   512
#define DIM1  513
#define PI_F  3.14159265358979f

// Output-vectorized concat, ILP=2, vector input loads.
// Each thread produces 2 aligned float4s of the flat [B*S*513] output,
// spaced blockDim apart (warp-coalesced STG.128). Input gathered with TWO
// INDEPENDENT LDG.128s (lo/hi, hi predicated on d!=0 only) + static select
// by d=c&3 (warp-uniform). Halves L1 wavefront traffic vs scalar gather
// while keeping bytes-in-flight and occupancy (regs ~30) unchanged.
//
// Per group (base=i4*4, r=base/513, c=base-513r, A=r*512+c, d=A&3=c&3):
//   fast path c<=508: out = floats A..A+3 = select(lo=in4[A>>2], hi=in4[A>>2+1], d)
//     bounds: needs A-d+7; for r<65535 next row exists; for r=65535, c≡1 (mod 4)
//     so max fast c=505 -> A-d+7 = last input float. Never OOB.
//   slow path c>=509 (~0.78%): scalar with pe channel at j==512-c.
__global__ __launch_bounds__(256) void pe_concat_kernel(
    const float* __restrict__ in,
    const int*   __restrict__ lengths,
    float*       __restrict__ out)
{
    const int i4_0 = blockIdx.x * 512 + threadIdx.x;
    const float4* __restrict__ in4 = reinterpret_cast<const float4*>(in);

    float4 o[2];
#pragma unroll
    for (int g = 0; g < 2; g++) {
        const int i4   = i4_0 + g * 256;
        const int base = i4 * 4;
        const int r    = base / DIM1;            // const-div -> mulhi
        const int c    = base - r * DIM1;
        const int kpe  = DIM - c;                // j-index of pe elem (may be >=4)

        if (kpe >= 4) {
            // fast path: two independent vector loads, static shift by d
            const int A = r * DIM + c;
            const int w = A >> 2;
            const int d = c & 3;                 // warp-uniform (== (-r)&3)
            const float4 lo = __ldg(in4 + w);
            float4 hi = lo;
            if (d) hi = __ldg(in4 + w + 1);      // independent of lo
            float4 v;
            if (d == 0)      v = lo;
            else if (d == 1) { v.x = lo.y; v.y = lo.z; v.z = lo.w; v.w = hi.x; }
            else if (d == 2) { v.x = lo.z; v.y = lo.w; v.z = hi.x; v.w = hi.y; }
            else             { v.x = lo.w; v.y = hi.x; v.z = hi.y; v.w = hi.z; }
            o[g] = v;
        } else {
            // slow path: window touches pe column (and maybe next row)
            const float* p = in + r * DIM + c;
            float v[4];
#pragma unroll
            for (int j = 0; j < 4; j++) {
                const int adj = (j > kpe) ? 1 : 0;
                v[j] = (j == kpe) ? 0.0f : __ldg(p + j - adj);
            }
            const int b = r >> 12;               // row / 4096
            const int s = r & (SEQ - 1);         // row % 4096
            const float fl   = (float)__ldg(lengths + b);
            const float safe = fmaxf(fl, 1.0f);
            v[kpe] = ((float)s < fl) ? __cosf(((float)s / safe) * PI_F) : 0.0f;
            o[g].x = v[0]; o[g].y = v[1]; o[g].z = v[2]; o[g].w = v[3];
        }
    }

    float4* out4 = reinterpret_cast<float4*>(out);
#pragma unroll
    for (int g = 0; g < 2; g++)
        out4[i4_0 + g * 256] = o[g];
}

extern "C" void kernel_launch(void* const* d_in, const int* in_sizes, int n_in,
                              void* d_out, int out_size)
{
    const float* in      = (const float*)d_in[0];   // [16, 4096, 512] f32
    const int*   lengths = (const int*)  d_in[1];   // [16] i32
    float*       out     = (float*)d_out;           // [16, 4096, 513] f32

    // out_size = 16*4096*513 = 33,619,968 floats = 8,404,992 float4
    //          = 16416 blocks * (256 threads * 2 float4), exact -> no bounds
    (void)in_sizes; (void)n_in; (void)out_size;
    pe_concat_kernel<<<16416, 256>>>(in, lengths, out);
}

// round 14
// speedup vs baseline: 1.0294x; 1.0288x over previous
#include <cuda_runtime.h>
#include <cuda_bf16.h>

#define SEQ   4096
#define DIM   512
#define DIM1  513
#define PI_F  3.14159265358979f
#define ILP   6

// Output-vectorized concat, ILP=6 scalar-gather (measured-best pattern).
// Each thread produces 6 aligned float4s of the flat [B*S*513] output,
// spaced blockDim apart (warp-coalesced STG.128). Input gathered with 24
// INDEPENDENT LDG.32 per thread -> deep warp-level MLP (the binding
// resource per R5/R6/R13 evidence; vector gathers reduce MLP and lose).
//
// Index identity per group (base=i4*4, r=base/513, c=base-513r):
//   output elem j in [0,4):  pe-channel iff j == 512-c
//   input addr             :  r*512 + c + j - (c+j >= 513)
// (a window never spans more than one row boundary since 513 > 4)
__global__ __launch_bounds__(256) void pe_concat_kernel(
    const float* __restrict__ in,
    const int*   __restrict__ lengths,
    float*       __restrict__ out)
{
    const int i4_0 = blockIdx.x * (256 * ILP) + threadIdx.x;

    float4 o[ILP];
#pragma unroll
    for (int g = 0; g < ILP; g++) {
        const int i4   = i4_0 + g * 256;
        const int base = i4 * 4;
        const int r    = base / DIM1;            // const-div -> mulhi
        const int c    = base - r * DIM1;
        const int kpe  = DIM - c;                // j-index of pe elem (may be >=4)
        const float* p = in + r * DIM + c;

        float v[4];
#pragma unroll
        for (int j = 0; j < 4; j++) {
            const int adj = (j > kpe) ? 1 : 0;   // skip over pe column
            v[j] = (j == kpe) ? 0.0f : __ldg(p + j - adj);
        }

        if (kpe < 4) {                           // ~0.78% of groups
            const int b = r >> 12;               // row / 4096
            const int s = r & (SEQ - 1);         // row % 4096
            const float fl   = (float)__ldg(lengths + b);
            const float safe = fmaxf(fl, 1.0f);
            v[kpe] = ((float)s < fl) ? __cosf(((float)s / safe) * PI_F) : 0.0f;
        }

        o[g].x = v[0]; o[g].y = v[1]; o[g].z = v[2]; o[g].w = v[3];
    }

    float4* out4 = reinterpret_cast<float4*>(out);
#pragma unroll
    for (int g = 0; g < ILP; g++)
        out4[i4_0 + g * 256] = o[g];
}

extern "C" void kernel_launch(void* const* d_in, const int* in_sizes, int n_in,
                              void* d_out, int out_size)
{
    const float* in      = (const float*)d_in[0];   // [16, 4096, 512] f32
    const int*   lengths = (const int*)  d_in[1];   // [16] i32
    float*       out     = (float*)d_out;           // [16, 4096, 513] f32

    // out_size = 16*4096*513 = 33,619,968 floats = 8,404,992 float4
    //          = 5472 blocks * (256 threads * 6 float4), exact -> no bounds
    (void)in_sizes; (void)n_in; (void)out_size;
    pe_concat_kernel<<<5472, 256>>>(in, lengths, out);
}

// round 15
// speedup vs baseline: 1.0343x; 1.0047x over previous
#include <cuda_runtime.h>
#include <cuda_bf16.h>

#define SEQ   4096
#define DIM   512
#define DIM1  513
#define PI_F  3.14159265358979f

// Output-vectorized concat, ILP=4 scalar-gather — the measured optimum across
// the full ILP sweep (1/2/4/6/8) and all structural variants (persistent,
// streaming hints, vector gathers). 16 independent LDG.32 per thread keeps
// warp-level MLP at the envelope; regs ~30 keeps occ ~72%. This round adds a
// fast path for the 99.2% of groups with no pe element: immediate-offset
// loads, no per-load predicate ALU.
//
// Index identity per group (base=i4*4, r=base/513, c=base-513r):
//   output elem j in [0,4):  pe-channel iff j == 512-c
//   input addr             :  r*512 + c + j - (c+j >= 513)
// (a window never spans more than one row boundary since 513 > 4)
__global__ __launch_bounds__(256) void pe_concat_kernel(
    const float* __restrict__ in,
    const int*   __restrict__ lengths,
    float*       __restrict__ out)
{
    const int i4_0 = blockIdx.x * 1024 + threadIdx.x;

    float4 o[4];
#pragma unroll
    for (int g = 0; g < 4; g++) {
        const int i4   = i4_0 + g * 256;
        const int base = i4 * 4;
        const int r    = base / DIM1;            // const-div -> mulhi
        const int c    = base - r * DIM1;
        const int kpe  = DIM - c;                // j-index of pe elem (may be >=4)
        const float* p = in + r * DIM + c;

        if (kpe >= 4) {
            // fast path (99.2% of groups): 4 independent loads, imm offsets
            o[g].x = __ldg(p + 0);
            o[g].y = __ldg(p + 1);
            o[g].z = __ldg(p + 2);
            o[g].w = __ldg(p + 3);
        } else {
            // window contains the pe column (and maybe start of next row)
            float v[4];
#pragma unroll
            for (int j = 0; j < 4; j++) {
                const int adj = (j > kpe) ? 1 : 0;   // skip over pe column
                v[j] = (j == kpe) ? 0.0f : __ldg(p + j - adj);
            }
            const int b = r >> 12;               // row / 4096
            const int s = r & (SEQ - 1);         // row % 4096
            const float fl   = (float)__ldg(lengths + b);
            const float safe = fmaxf(fl, 1.0f);
            v[kpe] = ((float)s < fl) ? __cosf(((float)s / safe) * PI_F) : 0.0f;
            o[g].x = v[0]; o[g].y = v[1]; o[g].z = v[2]; o[g].w = v[3];
        }
    }

    float4* out4 = reinterpret_cast<float4*>(out);
#pragma unroll
    for (int g = 0; g < 4; g++)
        out4[i4_0 + g * 256] = o[g];
}

extern "C" void kernel_launch(void* const* d_in, const int* in_sizes, int n_in,
                              void* d_out, int out_size)
{
    const float* in      = (const float*)d_in[0];   // [16, 4096, 512] f32
    const int*   lengths = (const int*)  d_in[1];   // [16] i32
    float*       out     = (float*)d_out;           // [16, 4096, 513] f32

    // out_size = 16*4096*513 = 33,619,968 floats = 8,404,992 float4
    //          = 8208 blocks * (256 threads * 4 float4), exact -> no bounds
    (void)in_sizes; (void)n_in; (void)out_size;
    pe_concat_kernel<<<8208, 256>>>(in, lengths, out);
}

// round 16
// speedup vs baseline: 1.0915x; 1.0553x over previous
#include <cuda_runtime.h>
#include <cuda_bf16.h>

#define SEQ   4096
#define DIM   512
#define DIM1  513
#define PI_F  3.14159265358979f

// Output-vectorized concat, ILP=4, phase-separated for maximal load batching.
// Evidence across R5/R13/R15: any branch interleaved with the gather splits
// the LDG batch and costs ~2-4us; the predicated straight-line form wins.
// This version makes the batching explicit:
//   phase 1: all 4 group descriptors (offset, kpe)
//   phase 2: all 16 independent predicated LDG.32, no intervening branches
//   phase 3: rare pe fixups (~0.78% of groups), after loads are in flight
//   phase 4: 4 coalesced STG.128
//
// Index identity per group (base=i4*4, r=base/513, c=base-513r):
//   output elem j in [0,4):  pe-channel iff j == 512-c
//   input addr             :  r*512 + c + j - (c+j >= 513)
__global__ __launch_bounds__(256) void pe_concat_kernel(
    const float* __restrict__ in,
    const int*   __restrict__ lengths,
    float*       __restrict__ out)
{
    const int i4_0 = blockIdx.x * 1024 + threadIdx.x;

    // ---- phase 1: descriptors ----
    int A[4];     // input base offset r*512+c
    int kpe[4];   // j-index of pe element (>=4 -> none in window)
#pragma unroll
    for (int g = 0; g < 4; g++) {
        const int base = (i4_0 + g * 256) * 4;
        const int r    = base / DIM1;            // const-div -> mulhi
        const int c    = base - r * DIM1;
        A[g]   = r * DIM + c;
        kpe[g] = DIM - c;
    }

    // ---- phase 2: 16 independent loads, straight-line ----
    float v[4][4];
#pragma unroll
    for (int g = 0; g < 4; g++) {
#pragma unroll
        for (int j = 0; j < 4; j++) {
            const int adj = (j > kpe[g]) ? 1 : 0;      // skip over pe column
            v[g][j] = __ldg(in + A[g] + j - adj);      // pe slot loads a
        }                                              // harmless in-bounds
    }                                                  // value, overwritten

    // ---- phase 3: pe fixups (rare), loads already in flight ----
#pragma unroll
    for (int g = 0; g < 4; g++) {
        if (kpe[g] < 4) {
            const int base = (i4_0 + g * 256) * 4;
            const int r    = base / DIM1;
            const int b    = r >> 12;                  // row / 4096
            const int s    = r & (SEQ - 1);            // row % 4096
            const float fl   = (float)__ldg(lengths + b);
            const float safe = fmaxf(fl, 1.0f);
            v[g][kpe[g]] = ((float)s < fl)
                         ? __cosf(((float)s / safe) * PI_F) : 0.0f;
        }
    }

    // ---- phase 4: coalesced vector stores ----
    float4* out4 = reinterpret_cast<float4*>(out);
#pragma unroll
    for (int g = 0; g < 4; g++) {
        float4 o;
        o.x = v[g][0]; o.y = v[g][1]; o.z = v[g][2]; o.w = v[g][3];
        out4[i4_0 + g * 256] = o;
    }
}

extern "C" void kernel_launch(void* const* d_in, const int* in_sizes, int n_in,
                              void* d_out, int out_size)
{
    const float* in      = (const float*)d_in[0];   // [16, 4096, 512] f32
    const int*   lengths = (const int*)  d_in[1];   // [16] i32
    float*       out     = (float*)d_out;           // [16, 4096, 513] f32

    // out_size = 16*4096*513 = 33,619,968 floats = 8,404,992 float4
    //          = 8208 blocks * (256 threads * 4 float4), exact -> no bounds
    (void)in_sizes; (void)n_in; (void)out_size;
    pe_concat_kernel<<<8208, 256>>>(in, lengths, out);
}